// round 5
// baseline (speedup 1.0000x reference)
#include <cuda_runtime.h>
#include <cstdint>

// Problem constants
#define NODES   64
#define FDIM    256
#define ODIM    256
#define BATCH   4096

// GEMM tiling
#define TILE_M  128
#define TILE_N  128
#define KCH     32      // fp32 K elements per chunk
#define NCHUNK  8       // 256 / 32
#define STAGES  3
#define THREADS 256

// SMEM: each tile row padded to 36 floats (144B) for conflict-free frag LDS
#define ROWPAD      36
#define TILE_BYTES  (128 * ROWPAD * 4)   // 18432
#define STAGE_BYTES (2 * TILE_BYTES)     // A tile + B tile = 36864
#define SMEM_BYTES  (STAGES * STAGE_BYTES)  // 110592

// 16 MB scratch for transposed TF32-rounded W: Wt[n][o][f] (K-major rows)
static __device__ float g_Wt[NODES * FDIM * ODIM];

__device__ __forceinline__ uint32_t smem_u32(const void* p) {
    uint32_t a;
    asm("{ .reg .u64 t; cvta.to.shared.u64 t, %1; cvt.u32.u64 %0, t; }" : "=r"(a) : "l"(p));
    return a;
}
__device__ __forceinline__ uint32_t cvt_tf32(float f) {
    uint32_t u;
    asm("cvt.rna.tf32.f32 %0, %1;" : "=r"(u) : "f"(f));
    return u;
}

// ---------------- W transpose + TF32 rounding prologue --------------------
// Wt[n][o][f] = round_tf32(W[n][f][o]); after this, HW tf32 truncation of B
// is a no-op (values already exactly representable).
__global__ void transpose_w_kernel(const float* __restrict__ W) {
    __shared__ float t[32][33];
    const int nn = blockIdx.z;
    const int f0 = blockIdx.x * 32, o0 = blockIdx.y * 32;
    const int tx = threadIdx.x, ty = threadIdx.y;  // 32 x 8
    const float* Wn = W + (size_t)nn * FDIM * ODIM;
    float* Wtn = g_Wt + (size_t)nn * FDIM * ODIM;
#pragma unroll
    for (int j = 0; j < 32; j += 8)
        t[ty + j][tx] = Wn[(size_t)(f0 + ty + j) * ODIM + (o0 + tx)];
    __syncthreads();
#pragma unroll
    for (int j = 0; j < 32; j += 8)
        Wtn[(size_t)(o0 + ty + j) * FDIM + (f0 + tx)] = __uint_as_float(cvt_tf32(t[tx][ty + j]));
}

// ---------------- tile loaders (cp.async, raw fp32) -----------------------
__device__ __forceinline__ void cp_tile_A(uint32_t dst, const float* __restrict__ x,
                                          int mbase, int node, int kc, int tid) {
#pragma unroll
    for (int t = 0; t < 4; t++) {
        const int i = t * THREADS + tid;            // 0..1023
        const int row = i >> 3, j = i & 7;          // 128 rows x 8 float4
        const float* src = x + ((size_t)(mbase + row) * NODES + node) * FDIM + kc * KCH + j * 4;
        const uint32_t d = dst + row * (ROWPAD * 4) + j * 16;
        asm volatile("cp.async.cg.shared.global [%0], [%1], 16;" :: "r"(d), "l"(src) : "memory");
    }
}

__device__ __forceinline__ void cp_tile_B(uint32_t dst, int node, int nbase, int kc, int tid) {
#pragma unroll
    for (int t = 0; t < 4; t++) {
        const int i = t * THREADS + tid;
        const int row = i >> 3, j = i & 7;          // 128 o-rows x 8 float4
        const float* src = g_Wt + (size_t)node * FDIM * ODIM + (size_t)(nbase + row) * FDIM +
                           kc * KCH + j * 4;
        const uint32_t d = dst + row * (ROWPAD * 4) + j * 16;
        asm volatile("cp.async.cg.shared.global [%0], [%1], 16;" :: "r"(d), "l"(src) : "memory");
    }
}

// ---------------- main GEMM kernel ----------------------------------------
extern "C" __global__ void __launch_bounds__(THREADS, 2)
node_mlp_kernel(const float* __restrict__ x, float* __restrict__ out) {
    extern __shared__ float smem[];
    const uint32_t sbase = smem_u32(smem);
    const int tid = threadIdx.x;
    const int wid = tid >> 5, lane = tid & 31;
    const int g = lane >> 2, t4 = lane & 3;         // mma groupID / threadID_in_group

    const int node  = blockIdx.z;
    const int nbase = blockIdx.y * TILE_N;
    const int mbase = blockIdx.x * TILE_M;

    const int warp_m = wid & 3, warp_n = wid >> 2;  // 4 x 2 warp grid
    const int m0 = warp_m * 32, n0 = warp_n * 64;   // warp tile 32x64

    float acc[2][8][4];
#pragma unroll
    for (int a = 0; a < 2; a++)
#pragma unroll
        for (int b = 0; b < 8; b++)
#pragma unroll
            for (int c = 0; c < 4; c++) acc[a][b][c] = 0.0f;

    // prologue: stage chunks 0..2
#pragma unroll
    for (int s = 0; s < STAGES; s++) {
        cp_tile_A(sbase + s * STAGE_BYTES, x, mbase, node, s, tid);
        cp_tile_B(sbase + s * STAGE_BYTES + TILE_BYTES, node, nbase, s, tid);
        asm volatile("cp.async.commit_group;" ::: "memory");
    }

#pragma unroll
    for (int kc = 0; kc < NCHUNK; kc++) {
        const int s = kc % STAGES;
        if (kc <= 5)      asm volatile("cp.async.wait_group 2;" ::: "memory");
        else if (kc == 6) asm volatile("cp.async.wait_group 1;" ::: "memory");
        else              asm volatile("cp.async.wait_group 0;" ::: "memory");
        __syncthreads();

        const float* As = smem + s * (STAGE_BYTES / 4);
        const float* Bs = As + (TILE_BYTES / 4);

#pragma unroll
        for (int ks = 0; ks < 4; ks++) {
            const int k0 = ks * 8;

            // A fragments (2 m-mmas), tf32-rounded in-register (rna, unbiased)
            uint32_t a[2][4];
#pragma unroll
            for (int mm = 0; mm < 2; mm++) {
                const int r = m0 + mm * 16 + g;
                a[mm][0] = cvt_tf32(As[(r)     * ROWPAD + k0 + t4]);
                a[mm][1] = cvt_tf32(As[(r + 8) * ROWPAD + k0 + t4]);
                a[mm][2] = cvt_tf32(As[(r)     * ROWPAD + k0 + t4 + 4]);
                a[mm][3] = cvt_tf32(As[(r + 8) * ROWPAD + k0 + t4 + 4]);
            }
            // B fragments (8 n-mmas); already tf32-exact from prologue
            uint32_t b[8][2];
#pragma unroll
            for (int nn = 0; nn < 8; nn++) {
                const int r = n0 + nn * 8 + g;
                b[nn][0] = __float_as_uint(Bs[r * ROWPAD + k0 + t4]);
                b[nn][1] = __float_as_uint(Bs[r * ROWPAD + k0 + t4 + 4]);
            }
#pragma unroll
            for (int mm = 0; mm < 2; mm++)
#pragma unroll
                for (int nn = 0; nn < 8; nn++) {
                    asm volatile(
                        "mma.sync.aligned.m16n8k8.row.col.f32.tf32.tf32.f32 "
                        "{%0,%1,%2,%3}, {%4,%5,%6,%7}, {%8,%9}, {%0,%1,%2,%3};"
                        : "+f"(acc[mm][nn][0]), "+f"(acc[mm][nn][1]),
                          "+f"(acc[mm][nn][2]), "+f"(acc[mm][nn][3])
                        : "r"(a[mm][0]), "r"(a[mm][1]), "r"(a[mm][2]), "r"(a[mm][3]),
                          "r"(b[nn][0]), "r"(b[nn][1]));
                }
        }
        __syncthreads();

        if (kc + STAGES < NCHUNK) {
            cp_tile_A(sbase + s * STAGE_BYTES, x, mbase, node, kc + STAGES, tid);
            cp_tile_B(sbase + s * STAGE_BYTES + TILE_BYTES, node, nbase, kc + STAGES, tid);
            asm volatile("cp.async.commit_group;" ::: "memory");
        }
    }

    // epilogue: scale by 1/sqrt(256) and store
    const float sc = 0.0625f;
#pragma unroll
    for (int mm = 0; mm < 2; mm++) {
#pragma unroll
        for (int half = 0; half < 2; half++) {
            const int rowg = m0 + mm * 16 + g + half * 8;
            float* orow = out + ((size_t)(mbase + rowg) * NODES + node) * ODIM + nbase;
#pragma unroll
            for (int nn = 0; nn < 8; nn++) {
                const int col = n0 + nn * 8 + 2 * t4;
                float2 v;
                v.x = acc[mm][nn][half * 2 + 0] * sc;
                v.y = acc[mm][nn][half * 2 + 1] * sc;
                __stcs(reinterpret_cast<float2*>(orow + col), v);
            }
        }
    }
}

// ---------------- launch ---------------------------------------------------
extern "C" void kernel_launch(void* const* d_in, const int* in_sizes, int n_in,
                              void* d_out, int out_size) {
    const float* x = (const float*)d_in[0];
    // d_in[1] = batch indices (implied by layout, unused)
    const float* W = (const float*)d_in[2];
    float* out = (float*)d_out;

    // 1) transpose + TF32-round W into g_Wt (K-major per node)
    transpose_w_kernel<<<dim3(FDIM / 32, ODIM / 32, NODES), dim3(32, 8)>>>(W);

    // 2) main tf32 mma.sync GEMM
    cudaFuncSetAttribute(node_mlp_kernel, cudaFuncAttributeMaxDynamicSharedMemorySize, SMEM_BYTES);
    node_mlp_kernel<<<dim3(BATCH / TILE_M, ODIM / TILE_N, NODES), THREADS, SMEM_BYTES>>>(x, out);
}

// round 17
// speedup vs baseline: 1.0821x; 1.0821x over previous
#include <cuda_runtime.h>
#include <cstdint>

// Problem constants
#define NODES   64
#define FDIM    256
#define ODIM    256
#define BATCH   4096

// GEMM tiling
#define TILE_M  128
#define TILE_N  128
#define KCH     32      // fp32 K elements per chunk
#define NCHUNK  8       // 256 / 32
#define STAGES  3
#define THREADS 256

// SMEM: A tile rows padded to 36 floats; B tile dense fragment-order (16 KB)
#define ROWPAD       36
#define A_TILE_BYTES (128 * ROWPAD * 4)       // 18432
#define B_TILE_BYTES (128 * KCH * 4)          // 16384
#define STAGE_BYTES  (A_TILE_BYTES + B_TILE_BYTES)   // 34816
#define SMEM_BYTES   (STAGES * STAGE_BYTES)          // 104448

// 16 MB scratch: W in fragment-order chunk layout (see transpose kernel)
// per node: [ntile(2)][kc(8)][ks(4)][r(128)][h(2)][4 floats]
static __device__ float g_Wt[NODES * FDIM * ODIM];

__device__ __forceinline__ uint32_t smem_u32(const void* p) {
    uint32_t a;
    asm("{ .reg .u64 t; cvta.to.shared.u64 t, %1; cvt.u32.u64 %0, t; }" : "=r"(a) : "l"(p));
    return a;
}
__device__ __forceinline__ uint32_t cvt_tf32(float f) {
    uint32_t u;
    asm("cvt.rna.tf32.f32 %0, %1;" : "=r"(u) : "f"(f));
    return u;
}

// ---------------- W transpose into fragment-order + TF32 rounding ---------
// For chunk c = ks*256 + r*2 + h (16B), contents are
//   [k=8ks+2h (lo half), k=8ks+2h+4 (hi), k=8ks+2h+1 (lo), k=8ks+2h+5 (hi)]
// so an mma B-pair (t4, t4+4) is one aligned float2 in smem.
__global__ void transpose_w_kernel(const float* __restrict__ W) {
    __shared__ float t[32][33];
    const int nn = blockIdx.z;
    const int kc = blockIdx.x;                 // f block of 32
    const int o0 = blockIdx.y * 32;
    const int tx = threadIdx.x, ty = threadIdx.y;  // 32 x 8
    const float* Wn = W + (size_t)nn * FDIM * ODIM;
#pragma unroll
    for (int j = 0; j < 32; j += 8)            // t[ff][oo] = W[kc*32+ff][o0+oo]
        t[ty + j][tx] = Wn[(size_t)(kc * 32 + ty + j) * ODIM + (o0 + tx)];
    __syncthreads();

    const int q  = ty * 32 + tx;               // 0..255 -> one 16B chunk
    const int ks = q >> 6;
    const int rr = (q & 63) >> 1;              // 0..31
    const int h  = q & 1;
    const int ntile = o0 >> 7;
    const int r  = (o0 & 127) + rr;

    float4 v;
    v.x = __uint_as_float(cvt_tf32(t[ks * 8 + 2 * h][rr]));      // t4=2h,   lo
    v.y = __uint_as_float(cvt_tf32(t[ks * 8 + 2 * h + 4][rr]));  // t4=2h,   hi
    v.z = __uint_as_float(cvt_tf32(t[ks * 8 + 2 * h + 1][rr]));  // t4=2h+1, lo
    v.w = __uint_as_float(cvt_tf32(t[ks * 8 + 2 * h + 5][rr]));  // t4=2h+1, hi
    float* dst = g_Wt + (size_t)nn * 65536 + ntile * 32768 + kc * 4096 +
                 ks * 1024 + r * 8 + h * 4;
    *reinterpret_cast<float4*>(dst) = v;
}

// ---------------- tile loaders (cp.async) ---------------------------------
__device__ __forceinline__ void cp_tile_A(uint32_t dst, const float* __restrict__ x,
                                          int mbase, int node, int kc, int tid) {
#pragma unroll
    for (int t = 0; t < 4; t++) {
        const int i = t * THREADS + tid;            // 0..1023
        const int row = i >> 3, j = i & 7;          // 128 rows x 8 float4
        const float* src = x + ((size_t)(mbase + row) * NODES + node) * FDIM + kc * KCH + j * 4;
        const uint32_t d = dst + row * (ROWPAD * 4) + j * 16;
        asm volatile("cp.async.cg.shared.global [%0], [%1], 16;" :: "r"(d), "l"(src) : "memory");
    }
}

__device__ __forceinline__ void cp_tile_B(uint32_t dst, int node, int nbase, int kc, int tid) {
    const float* base = g_Wt + (size_t)node * 65536 + (nbase >> 7) * 32768 + kc * 4096;
#pragma unroll
    for (int t = 0; t < 4; t++) {
        const int c = t * THREADS + tid;            // chunk 0..1023
        asm volatile("cp.async.cg.shared.global [%0], [%1], 16;"
                     :: "r"(dst + c * 16), "l"(base + c * 4) : "memory");
    }
}

// ---------------- main GEMM kernel ----------------------------------------
extern "C" __global__ void __launch_bounds__(THREADS, 2)
node_mlp_kernel(const float* __restrict__ x, float* __restrict__ out) {
    extern __shared__ float smem[];
    const uint32_t sbase = smem_u32(smem);
    const int tid = threadIdx.x;
    const int wid = tid >> 5, lane = tid & 31;
    const int g = lane >> 2, t4 = lane & 3;

    const int node  = blockIdx.z;
    const int nbase = blockIdx.y * TILE_N;
    const int mbase = blockIdx.x * TILE_M;

    const int warp_m = wid & 3, warp_n = wid >> 2;  // 4 x 2 warp grid
    const int m0 = warp_m * 32, n0 = warp_n * 64;   // warp tile 32x64

    float acc[2][8][4];
#pragma unroll
    for (int a = 0; a < 2; a++)
#pragma unroll
        for (int b = 0; b < 8; b++)
#pragma unroll
            for (int c = 0; c < 4; c++) acc[a][b][c] = 0.0f;

    // prologue: stage chunks 0,1 (STAGES-1 in flight)
#pragma unroll
    for (int s = 0; s < STAGES - 1; s++) {
        cp_tile_A(sbase + s * STAGE_BYTES, x, mbase, node, s, tid);
        cp_tile_B(sbase + s * STAGE_BYTES + A_TILE_BYTES, node, nbase, s, tid);
        asm volatile("cp.async.commit_group;" ::: "memory");
    }

#pragma unroll
    for (int kc = 0; kc < NCHUNK; kc++) {
        const int s = kc % STAGES;
        if (kc < NCHUNK - 1) asm volatile("cp.async.wait_group 1;" ::: "memory");
        else                 asm volatile("cp.async.wait_group 0;" ::: "memory");
        __syncthreads();   // chunk kc visible to all; all warps done with chunk kc-1

        // issue loads for chunk kc+2 into buffer freed by chunk kc-1;
        // transfer overlaps the mmas below
        if (kc + 2 < NCHUNK) {
            const int sw = (kc + 2) % STAGES;
            cp_tile_A(sbase + sw * STAGE_BYTES, x, mbase, node, kc + 2, tid);
            cp_tile_B(sbase + sw * STAGE_BYTES + A_TILE_BYTES, node, nbase, kc + 2, tid);
            asm volatile("cp.async.commit_group;" ::: "memory");
        }

        const float* As = smem + s * (STAGE_BYTES / 4);
        const char*  Bs = reinterpret_cast<const char*>(smem) + s * STAGE_BYTES + A_TILE_BYTES;

#pragma unroll
        for (int ks = 0; ks < 4; ks++) {
            const int k0 = ks * 8;

            // A fragments (scalar LDS, conflict-free; rna-rounded to tf32)
            uint32_t a[2][4];
#pragma unroll
            for (int mm = 0; mm < 2; mm++) {
                const int r = m0 + mm * 16 + g;
                a[mm][0] = cvt_tf32(As[(r)     * ROWPAD + k0 + t4]);
                a[mm][1] = cvt_tf32(As[(r + 8) * ROWPAD + k0 + t4]);
                a[mm][2] = cvt_tf32(As[(r)     * ROWPAD + k0 + t4 + 4]);
                a[mm][3] = cvt_tf32(As[(r + 8) * ROWPAD + k0 + t4 + 4]);
            }
            // B fragments: one aligned float2 per nn (fragment-order layout)
            uint32_t b[8][2];
            const char* bp = Bs + ks * 4096 + (n0 + g) * 32 + (t4 >> 1) * 16 + (t4 & 1) * 8;
#pragma unroll
            for (int nn = 0; nn < 8; nn++) {
                const float2 bv = *reinterpret_cast<const float2*>(bp + nn * 256);
                b[nn][0] = __float_as_uint(bv.x);
                b[nn][1] = __float_as_uint(bv.y);
            }
#pragma unroll
            for (int mm = 0; mm < 2; mm++)
#pragma unroll
                for (int nn = 0; nn < 8; nn++) {
                    asm volatile(
                        "mma.sync.aligned.m16n8k8.row.col.f32.tf32.tf32.f32 "
                        "{%0,%1,%2,%3}, {%4,%5,%6,%7}, {%8,%9}, {%0,%1,%2,%3};"
                        : "+f"(acc[mm][nn][0]), "+f"(acc[mm][nn][1]),
                          "+f"(acc[mm][nn][2]), "+f"(acc[mm][nn][3])
                        : "r"(a[mm][0]), "r"(a[mm][1]), "r"(a[mm][2]), "r"(a[mm][3]),
                          "r"(b[nn][0]), "r"(b[nn][1]));
                }
        }
    }

    // epilogue: scale by 1/sqrt(256) and store
    const float sc = 0.0625f;
#pragma unroll
    for (int mm = 0; mm < 2; mm++) {
#pragma unroll
        for (int half = 0; half < 2; half++) {
            const int rowg = m0 + mm * 16 + g + half * 8;
            float* orow = out + ((size_t)(mbase + rowg) * NODES + node) * ODIM + nbase;
#pragma unroll
            for (int nn = 0; nn < 8; nn++) {
                const int col = n0 + nn * 8 + 2 * t4;
                float2 v;
                v.x = acc[mm][nn][half * 2 + 0] * sc;
                v.y = acc[mm][nn][half * 2 + 1] * sc;
                __stcs(reinterpret_cast<float2*>(orow + col), v);
            }
        }
    }
}

// ---------------- launch ---------------------------------------------------
extern "C" void kernel_launch(void* const* d_in, const int* in_sizes, int n_in,
                              void* d_out, int out_size) {
    const float* x = (const float*)d_in[0];
    // d_in[1] = batch indices (implied by layout, unused)
    const float* W = (const float*)d_in[2];
    float* out = (float*)d_out;

    // 1) transpose + TF32-round W into fragment-order g_Wt
    transpose_w_kernel<<<dim3(NCHUNK, ODIM / 32, NODES), dim3(32, 8)>>>(W);

    // 2) main tf32 mma.sync GEMM
    cudaFuncSetAttribute(node_mlp_kernel, cudaFuncAttributeMaxDynamicSharedMemorySize, SMEM_BYTES);
    node_mlp_kernel<<<dim3(BATCH / TILE_M, ODIM / TILE_N, NODES), THREADS, SMEM_BYTES>>>(x, out);
}